// round 8
// baseline (speedup 1.0000x reference)
#include <cuda_runtime.h>
#include <math.h>

#define Bb 2
#define Dd 192
#define Hh 56
#define Ww 56
#define Nn 16
#define Rr 12
#define Kk 4
#define LL (Hh*Ww)      /* 3136 */
#define TP 64           /* positions per prep tile */
#define CH 44           /* R + 2N */
#define CHP 48          /* padded channels */
#define PF 64           /* scan prefetch pad rows */
#define XSTR 196        /* xs smem row stride (words) */
#define DSTR 68         /* dblS row stride (16B-aligned rows) */

typedef unsigned long long u64;

// ---------------- device scratch (static, no runtime alloc) ----------------
__device__ float2 g_dz[2*Bb*Kk*LL*Dd + PF*Dd];   // (softplus(delta), delta*u), traversal order
__device__ float2 g_BC[2*Bb*Kk*LL*16 + PF*16];   // per (row,n): {B_n(own), C_n(cross)}
__device__ float  g_yk[2*Bb*Kk*LL*Dd];           // per-direction scan outputs (traversal idx)
__device__ float  g_xT[2*Bb*LL*Dd];              // x transposed to [pos][d] (canonical)

__device__ __forceinline__ float ex2(float x) {
    float r; asm("ex2.approx.ftz.f32 %0, %1;" : "=f"(r) : "f"(x)); return r;
}
__device__ __forceinline__ float lg2(float x) {
    float r; asm("lg2.approx.ftz.f32 %0, %1;" : "=f"(r) : "f"(x)); return r;
}
__device__ __forceinline__ u64 ffma2(u64 a, u64 b, u64 c) {
    u64 r; asm("fma.rn.f32x2 %0, %1, %2, %3;" : "=l"(r) : "l"(a), "l"(b), "l"(c)); return r;
}
__device__ __forceinline__ float hadd2(u64 v) {
    float lo, hi; asm("mov.b64 {%0, %1}, %2;" : "=f"(lo), "=f"(hi) : "l"(v)); return lo + hi;
}
#define LOG2E 1.44269504088896340736f
#define LN2   0.69314718055994530942f

__device__ __forceinline__ int tau_of(int k, int pos) {
    int t1 = (pos % Ww) * Hh + pos / Ww;
    switch (k) {
        case 0: return pos;
        case 1: return t1;
        case 2: return LL - 1 - pos;
        default: return LL - 1 - t1;
    }
}

// ---------------- kernel 1: projections + precompute ----------------
// grid (49, K, SB), 256 threads. GEMM: thread=(pg,cb), 4 pos x 3 ch, f32x2 packed.
// Epilogue: thread=(pq,dg), 4 consecutive positions per thread, LDS.128.
__global__ void __launch_bounds__(256, 2)
prep_kernel(const float* __restrict__ x1, const float* __restrict__ x2,
            const float* __restrict__ pw1, const float* __restrict__ pw2,
            const float* __restrict__ dtw1, const float* __restrict__ dtw2,
            const float* __restrict__ dtb1, const float* __restrict__ dtb2)
{
    extern __shared__ float sm[];
    float* xs   = sm;                    // [TP][XSTR]
    float* Ws   = xs + TP*XSTR;          // [48][192]
    float* dtws = Ws + CHP*Dd;           // [192][12] packed
    float* bsm  = dtws + Dd*12;          // [192]
    float* dblS = bsm + Dd;              // [48][DSTR]

    const int t    = threadIdx.x;
    const int pos0 = blockIdx.x * TP;
    const int k    = blockIdx.y;
    const int sbz  = blockIdx.z;
    const int s    = sbz >> 1, b = sbz & 1;
    const float* x   = s ? x2   : x1;
    const float* pw  = s ? pw2  : pw1;
    const float* dtw = s ? dtw2 : dtw1;
    const float* dtb = s ? dtb2 : dtb1;
    const int sb  = s*2 + b;
    const int sbo = (s^1)*2 + b;

    for (int e = t; e < Dd*TP; e += 256) {
        int d = e / TP, p = e % TP;
        xs[p*XSTR + d] = x[(b*Dd + d)*LL + pos0 + p];
    }
    for (int e = t; e < CHP*Dd; e += 256) Ws[e] = (e < CH*Dd) ? pw[k*CH*Dd + e] : 0.f;
    for (int e = t; e < Dd*Rr; e += 256) dtws[e] = dtw[k*Dd*Rr + e];
    if (t < Dd) bsm[t] = dtb[k*Dd + t];
    __syncthreads();

    if (k == 0) {
        for (int e = t; e < TP*Dd; e += 256) {
            int p = e / Dd, d = e - p*Dd;
            g_xT[(size_t)(sb*LL + pos0 + p)*Dd + d] = xs[p*XSTR + d];
        }
    }

    const int pg = t & 15;
    const int cb = t >> 4;

    // ---- GEMM: dbl[c][p] = sum_d W[c][d] * x[d][p] ----
    {
        u64 acc2[4][3];
        #pragma unroll
        for (int i = 0; i < 4; i++)
            #pragma unroll
            for (int j = 0; j < 3; j++) acc2[i][j] = 0ull;

        #pragma unroll 2
        for (int d4 = 0; d4 < Dd; d4 += 4) {
            ulonglong2 w0 = *(const ulonglong2*)&Ws[ cb      *Dd + d4];
            ulonglong2 w1 = *(const ulonglong2*)&Ws[(cb+16) *Dd + d4];
            ulonglong2 w2 = *(const ulonglong2*)&Ws[(cb+32) *Dd + d4];
            #pragma unroll
            for (int i = 0; i < 4; i++) {
                ulonglong2 xv = *(const ulonglong2*)&xs[(pg + 16*i)*XSTR + d4];
                acc2[i][0] = ffma2(xv.x, w0.x, acc2[i][0]);
                acc2[i][0] = ffma2(xv.y, w0.y, acc2[i][0]);
                acc2[i][1] = ffma2(xv.x, w1.x, acc2[i][1]);
                acc2[i][1] = ffma2(xv.y, w1.y, acc2[i][1]);
                acc2[i][2] = ffma2(xv.x, w2.x, acc2[i][2]);
                acc2[i][2] = ffma2(xv.y, w2.y, acc2[i][2]);
            }
        }
        #pragma unroll
        for (int i = 0; i < 4; i++) {
            dblS[ cb     *DSTR + pg + 16*i] = hadd2(acc2[i][0]);
            dblS[(cb+16) *DSTR + pg + 16*i] = hadd2(acc2[i][1]);
            dblS[(cb+32) *DSTR + pg + 16*i] = hadd2(acc2[i][2]);
        }
    }
    __syncthreads();

    // ---- store B(own .x)/C(cross .y) per n, traversal order ----
    for (int e = t; e < TP*16; e += 256) {
        int p = e >> 4, n = e & 15;
        int tauv = tau_of(k, pos0 + p);
        float* bx = (float*)&g_BC[((size_t)(sb *Kk + k)*LL + tauv)*16 + n];
        float* cy = (float*)&g_BC[((size_t)(sbo*Kk + k)*LL + tauv)*16 + n];
        bx[0] = dblS[(12+n)*DSTR + p];
        cy[1] = dblS[(28+n)*DSTR + p];
    }

    // ---- dt epilogue: 4 consecutive positions per thread, vectorized LDS.128 ----
    {
        const int pq = t & 15;
        const int dg = t >> 4;
        const int p4 = pq * 4;
        const size_t rowb = (size_t)(sb*Kk + k)*LL;
        #pragma unroll 2
        for (int dd = 0; dd < 12; dd++) {
            const int d = dd*16 + dg;
            const float4* dw = (const float4*)&dtws[d*12];
            const float4 wa = dw[0], wb = dw[1], wc = dw[2];
            float4 rr[12];
            #pragma unroll
            for (int r = 0; r < 12; r++) rr[r] = *(const float4*)&dblS[r*DSTR + p4];
            const float bias = bsm[d];
            float a4[4];
            #pragma unroll
            for (int i = 0; i < 4; i++) {
                const float* q = (const float*)rr;    // rr[r] components
                float a = bias;
                a = fmaf(wa.x, ((const float*)&rr[0])[i],  a);
                a = fmaf(wa.y, ((const float*)&rr[1])[i],  a);
                a = fmaf(wa.z, ((const float*)&rr[2])[i],  a);
                a = fmaf(wa.w, ((const float*)&rr[3])[i],  a);
                a = fmaf(wb.x, ((const float*)&rr[4])[i],  a);
                a = fmaf(wb.y, ((const float*)&rr[5])[i],  a);
                a = fmaf(wb.z, ((const float*)&rr[6])[i],  a);
                a = fmaf(wb.w, ((const float*)&rr[7])[i],  a);
                a = fmaf(wc.x, ((const float*)&rr[8])[i],  a);
                a = fmaf(wc.y, ((const float*)&rr[9])[i],  a);
                a = fmaf(wc.z, ((const float*)&rr[10])[i], a);
                a = fmaf(wc.w, ((const float*)&rr[11])[i], a);
                (void)q;
                a4[i] = a;
            }
            #pragma unroll
            for (int i = 0; i < 4; i++) {
                float a = a4[i];
                float em = ex2(-fabsf(a) * LOG2E);
                float sp = fmaxf(a, 0.f) + lg2(1.f + em) * LN2;
                float z  = sp * xs[(p4 + i)*XSTR + d];
                int tauv = tau_of(k, pos0 + p4 + i);
                g_dz[(rowb + tauv)*Dd + d] = make_float2(sp, z);
            }
        }
    }
}

// ---------------- kernel 2: selective scan (1 state/lane, register triple-buffer) ----------------
// grid (24, K, SB), 128 threads (4 warps). Warp w: chains d = bx*8 + w*2 + dl.
// lane = dl*16 + n: state n of chain d. 1 ex2 per lane per step.
__global__ void __launch_bounds__(128, 3) scan_kernel(const float* __restrict__ A1,
                                                      const float* __restrict__ A2)
{
    const int tid  = threadIdx.x;
    const int w    = tid >> 5;
    const int lane = tid & 31;
    const int dl = lane >> 4, n = lane & 15;
    const int k  = blockIdx.y;
    const int sb = blockIdx.z;
    const int s  = sb >> 1;
    const int d  = blockIdx.x*8 + w*2 + dl;

    const float* Alog = s ? A2 : A1;
    const float a = -__expf(Alog[(k*Dd + d)*Nn + n]) * LOG2E;

    const int row0 = (sb*Kk + k)*LL;
    const float2* dzp = g_dz + (size_t)row0*Dd + d;   // row stride Dd float2
    const float2* bcp = g_BC + (size_t)row0*16 + n;   // row stride 16 float2
    float* yp = g_yk + (size_t)row0*Dd + d;

    const int  s0     = ((n & 1) << 2) | (n & 2) | ((n & 4) >> 2);
    const bool storer = (n < 8);

    float2 dzb[3][8], bcb[3][8];
    #pragma unroll
    for (int sl = 0; sl < 2; sl++)
        #pragma unroll
        for (int j = 0; j < 8; j++) {
            dzb[sl][j] = dzp[(size_t)(sl*8 + j)*Dd];
            bcb[sl][j] = bcp[(size_t)(sl*8 + j)*16];
        }

    float h = 0.f;

    #define SCAN_BODY(IT, SL, PFS) do {                                          \
        const int tt = (IT)*8;                                                   \
        _Pragma("unroll")                                                        \
        for (int j = 0; j < 8; j++) {                                            \
            dzb[PFS][j] = dzp[(size_t)(tt + 16 + j)*Dd];                         \
            bcb[PFS][j] = bcp[(size_t)(tt + 16 + j)*16];                         \
        }                                                                        \
        float e[8], u[8], Cv[8], y[8];                                           \
        _Pragma("unroll")                                                        \
        for (int j = 0; j < 8; j++) {                                            \
            e[j]  = ex2(dzb[SL][j].x * a);                                       \
            u[j]  = dzb[SL][j].y * bcb[SL][j].x;                                 \
            Cv[j] = bcb[SL][j].y;                                                \
        }                                                                        \
        _Pragma("unroll")                                                        \
        for (int j = 0; j < 8; j++) {                                            \
            h = fmaf(e[j], h, u[j]);                                             \
            y[j] = h * Cv[j];                                                    \
        }                                                                        \
        _Pragma("unroll")                                                        \
        for (int j = 0; j < 4; j++) {                                            \
            float send = (n & 1) ? y[j] : y[4 + j];                              \
            float recv = __shfl_xor_sync(0xffffffffu, send, 1);                  \
            y[j] = ((n & 1) ? y[4 + j] : y[j]) + recv;                           \
        }                                                                        \
        _Pragma("unroll")                                                        \
        for (int j = 0; j < 2; j++) {                                            \
            float send = (n & 2) ? y[j] : y[2 + j];                              \
            float recv = __shfl_xor_sync(0xffffffffu, send, 2);                  \
            y[j] = ((n & 2) ? y[2 + j] : y[j]) + recv;                           \
        }                                                                        \
        {                                                                        \
            float send = (n & 4) ? y[0] : y[1];                                  \
            float recv = __shfl_xor_sync(0xffffffffu, send, 4);                  \
            float y0 = ((n & 4) ? y[1] : y[0]) + recv;                           \
            float tot = y0 + __shfl_xor_sync(0xffffffffu, y0, 8);                \
            if (storer && tt < LL) yp[(size_t)(tt + s0)*Dd] = tot;               \
        }                                                                        \
    } while (0)

    // 392 real tiles + 1 pad tile (multiple of 3); pads are zeros -> harmless
    for (int base = 0; base < 393; base += 3) {
        SCAN_BODY(base + 0, 0, 2);
        SCAN_BODY(base + 1, 1, 0);
        SCAN_BODY(base + 2, 2, 1);
    }
    #undef SCAN_BODY
}

// ---------------- kernel 3: merge (sum k) + D*u + LayerNorm ----------------
__global__ void merge_ln_kernel(const float* __restrict__ D1s, const float* __restrict__ D2s,
                                const float* __restrict__ lnw, const float* __restrict__ lnb,
                                float* __restrict__ out)
{
    __shared__ float red[6];
    const int rid = blockIdx.x;
    const int sb = rid / LL, pos = rid % LL;
    const int s = sb >> 1;
    const int d = threadIdx.x;
    const float* Ds = s ? D2s : D1s;

    const int t1 = (pos % Ww) * Hh + pos / Ww;
    const int base = sb*Kk*LL;
    float v = g_yk[(size_t)(base          + pos       )*Dd + d]
            + g_yk[(size_t)(base + 1*LL   + t1        )*Dd + d]
            + g_yk[(size_t)(base + 2*LL   + (LL-1-pos))*Dd + d]
            + g_yk[(size_t)(base + 3*LL   + (LL-1-t1) )*Dd + d];
    const float Dsum = Ds[d] + Ds[Dd + d] + Ds[2*Dd + d] + Ds[3*Dd + d];
    v = fmaf(Dsum, g_xT[(size_t)(sb*LL + pos)*Dd + d], v);

    float tsum = v;
    #pragma unroll
    for (int o = 16; o; o >>= 1) tsum += __shfl_xor_sync(0xffffffffu, tsum, o);
    if ((d & 31) == 0) red[d >> 5] = tsum;
    __syncthreads();
    const float mu = (red[0]+red[1]+red[2]+red[3]+red[4]+red[5]) * (1.f/192.f);
    const float dv = v - mu;
    __syncthreads();
    float q = dv*dv;
    #pragma unroll
    for (int o = 16; o; o >>= 1) q += __shfl_xor_sync(0xffffffffu, q, o);
    if ((d & 31) == 0) red[d >> 5] = q;
    __syncthreads();
    const float var = (red[0]+red[1]+red[2]+red[3]+red[4]+red[5]) * (1.f/192.f);

    out[rid*Dd + d] = dv * rsqrtf(var + 1e-5f) * lnw[d] + lnb[d];
}

// ---------------- launch ----------------
extern "C" void kernel_launch(void* const* d_in, const int* in_sizes, int n_in,
                              void* d_out, int out_size)
{
    const float* x1   = (const float*)d_in[0];
    const float* x2   = (const float*)d_in[1];
    const float* pw1  = (const float*)d_in[2];
    const float* pw2  = (const float*)d_in[3];
    const float* dtw1 = (const float*)d_in[4];
    const float* dtw2 = (const float*)d_in[5];
    const float* dtb1 = (const float*)d_in[6];
    const float* dtb2 = (const float*)d_in[7];
    const float* A1   = (const float*)d_in[8];
    const float* A2   = (const float*)d_in[9];
    const float* D1s  = (const float*)d_in[10];
    const float* D2s  = (const float*)d_in[11];
    const float* lnw  = (const float*)d_in[12];
    const float* lnb  = (const float*)d_in[13];
    float* out = (float*)d_out;

    const int smem = (TP*XSTR + CHP*Dd + Dd*12 + Dd + CHP*DSTR) * (int)sizeof(float); // 110,080 B
    cudaFuncSetAttribute(prep_kernel, cudaFuncAttributeMaxDynamicSharedMemorySize, smem);

    prep_kernel<<<dim3(LL/TP, Kk, 4), 256, smem>>>(x1, x2, pw1, pw2, dtw1, dtw2, dtb1, dtb2);
    scan_kernel<<<dim3(Dd/8, Kk, 2*Bb), 128>>>(A1, A2);
    merge_ln_kernel<<<2*Bb*LL, Dd>>>(D1s, D2s, lnw, lnb, out);
}

// round 9
// speedup vs baseline: 1.4105x; 1.4105x over previous
#include <cuda_runtime.h>
#include <math.h>

#define Bb 2
#define Dd 192
#define Hh 56
#define Ww 56
#define Nn 16
#define Rr 12
#define Kk 4
#define LL (Hh*Ww)      /* 3136 */
#define LLP 3200        /* padded chain length for dz (prefetch overrun) */
#define TP 64           /* positions per prep tile */
#define CH 44           /* R + 2N */
#define CHP 48          /* padded channels */
#define PF 64           /* BC prefetch pad rows */
#define XSTR 196        /* xs smem row stride (words) */
#define DSTR 66         /* dblS row stride */
#define ST 16           /* scan steps per tile */
#define NT (LL/ST)      /* 196 tiles */

typedef unsigned long long u64;

// ---------------- device scratch (static, no runtime alloc) ----------------
// dz, yk in chunk-major layout: [sbk(16)][d-chunk(48)][t][4 d] -> dense warp tiles.
__device__ float2 g_dz[16*48*LLP*4];             // (softplus(delta), delta*u)
__device__ float2 g_BC[2*Bb*Kk*LL*16 + PF*16];   // per (row,no): {B_no,B_no+8},{C_no,C_no+8}
__device__ float  g_yk[16*48*LL*4];              // per-direction scan outputs
__device__ float  g_xT[2*Bb*LL*Dd];              // x transposed to [pos][d] (canonical)

__device__ __forceinline__ float ex2(float x) {
    float r; asm("ex2.approx.ftz.f32 %0, %1;" : "=f"(r) : "f"(x)); return r;
}
__device__ __forceinline__ float lg2(float x) {
    float r; asm("lg2.approx.ftz.f32 %0, %1;" : "=f"(r) : "f"(x)); return r;
}
__device__ __forceinline__ u64 ffma2(u64 a, u64 b, u64 c) {
    u64 r; asm("fma.rn.f32x2 %0, %1, %2, %3;" : "=l"(r) : "l"(a), "l"(b), "l"(c)); return r;
}
__device__ __forceinline__ float hadd2(u64 v) {
    float lo, hi; asm("mov.b64 {%0, %1}, %2;" : "=f"(lo), "=f"(hi) : "l"(v)); return lo + hi;
}
#define LOG2E 1.44269504088896340736f
#define LN2   0.69314718055994530942f

__device__ __forceinline__ int tau_of(int k, int pos) {
    int t1 = (pos % Ww) * Hh + pos / Ww;
    switch (k) {
        case 0: return pos;
        case 1: return t1;
        case 2: return LL - 1 - pos;
        default: return LL - 1 - t1;
    }
}

// ---------------- kernel 1: projections + precompute ----------------
__global__ void __launch_bounds__(256, 2)
prep_kernel(const float* __restrict__ x1, const float* __restrict__ x2,
            const float* __restrict__ pw1, const float* __restrict__ pw2,
            const float* __restrict__ dtw1, const float* __restrict__ dtw2,
            const float* __restrict__ dtb1, const float* __restrict__ dtb2)
{
    extern __shared__ float sm[];
    float* xs   = sm;                    // [TP][XSTR]
    float* Ws   = xs + TP*XSTR;          // [48][192]
    float* dtws = Ws + CHP*Dd;           // [192][12] packed
    float* bsm  = dtws + Dd*12;          // [192]
    float* dblS = bsm + Dd;              // [48][DSTR]

    const int t    = threadIdx.x;
    const int pos0 = blockIdx.x * TP;
    const int k    = blockIdx.y;
    const int sbz  = blockIdx.z;
    const int s    = sbz >> 1, b = sbz & 1;
    const float* x   = s ? x2   : x1;
    const float* pw  = s ? pw2  : pw1;
    const float* dtw = s ? dtw2 : dtw1;
    const float* dtb = s ? dtb2 : dtb1;
    const int sb  = s*2 + b;
    const int sbo = (s^1)*2 + b;

    // stage x (vectorized over positions) and weights
    for (int e = t; e < Dd*(TP/4); e += 256) {
        int d = e >> 4, p4 = (e & 15) * 4;
        float4 v = *(const float4*)&x[(size_t)(b*Dd + d)*LL + pos0 + p4];
        xs[(p4+0)*XSTR + d] = v.x;
        xs[(p4+1)*XSTR + d] = v.y;
        xs[(p4+2)*XSTR + d] = v.z;
        xs[(p4+3)*XSTR + d] = v.w;
    }
    for (int e = t; e < CHP*Dd/4; e += 256) {
        float4 v = (e < CH*Dd/4) ? ((const float4*)pw)[(size_t)k*(CH*Dd/4) + e]
                                 : make_float4(0.f,0.f,0.f,0.f);
        ((float4*)Ws)[e] = v;
    }
    for (int e = t; e < Dd*Rr/4; e += 256)
        ((float4*)dtws)[e] = ((const float4*)dtw)[(size_t)k*(Dd*Rr/4) + e];
    if (t < Dd) bsm[t] = dtb[k*Dd + t];
    __syncthreads();

    if (k == 0) {
        for (int e = t; e < TP*Dd; e += 256) {
            int p = e / Dd, d = e - p*Dd;
            g_xT[(size_t)(sb*LL + pos0 + p)*Dd + d] = xs[p*XSTR + d];
        }
    }

    const int pg = t & 15;
    const int cb = t >> 4;

    // ---- GEMM: dbl[c][p] = sum_d W[c][d] * x[d][p]; 4 pos x 3 ch, f32x2 packed ----
    {
        u64 acc2[4][3];
        #pragma unroll
        for (int i = 0; i < 4; i++)
            #pragma unroll
            for (int j = 0; j < 3; j++) acc2[i][j] = 0ull;

        #pragma unroll 2
        for (int d4 = 0; d4 < Dd; d4 += 4) {
            ulonglong2 w0 = *(const ulonglong2*)&Ws[ cb      *Dd + d4];
            ulonglong2 w1 = *(const ulonglong2*)&Ws[(cb+16) *Dd + d4];
            ulonglong2 w2 = *(const ulonglong2*)&Ws[(cb+32) *Dd + d4];
            #pragma unroll
            for (int i = 0; i < 4; i++) {
                ulonglong2 xv = *(const ulonglong2*)&xs[(pg + 16*i)*XSTR + d4];
                acc2[i][0] = ffma2(xv.x, w0.x, acc2[i][0]);
                acc2[i][0] = ffma2(xv.y, w0.y, acc2[i][0]);
                acc2[i][1] = ffma2(xv.x, w1.x, acc2[i][1]);
                acc2[i][1] = ffma2(xv.y, w1.y, acc2[i][1]);
                acc2[i][2] = ffma2(xv.x, w2.x, acc2[i][2]);
                acc2[i][2] = ffma2(xv.y, w2.y, acc2[i][2]);
            }
        }
        #pragma unroll
        for (int i = 0; i < 4; i++) {
            dblS[ cb     *DSTR + pg + 16*i] = hadd2(acc2[i][0]);
            dblS[(cb+16) *DSTR + pg + 16*i] = hadd2(acc2[i][1]);
            dblS[(cb+32) *DSTR + pg + 16*i] = hadd2(acc2[i][2]);
        }
    }
    __syncthreads();

    // ---- store packed B(own)/C(cross), traversal order, n-paired (no, no+8) ----
    for (int e = t; e < TP*8; e += 256) {
        int p = e >> 3, no = e & 7;
        int tauv = tau_of(k, pos0 + p);
        float2 bv = make_float2(dblS[(12+no)*DSTR+p], dblS[(20+no)*DSTR+p]);
        float2 cv = make_float2(dblS[(28+no)*DSTR+p], dblS[(36+no)*DSTR+p]);
        g_BC[((size_t)(sb *Kk + k)*LL + tauv)*16 + no*2    ] = bv;
        g_BC[((size_t)(sbo*Kk + k)*LL + tauv)*16 + no*2 + 1] = cv;
    }

    // ---- dt = dtw @ dbl[0:12] + bias, softplus, z = dt*u ; chunk-major store ----
    {
        const size_t sbk48 = (size_t)(sb*Kk + k)*48;
        for (int e = t; e < TP*Dd; e += 256) {
            int p = e / Dd, d = e - p*Dd;
            const float4* dw = (const float4*)&dtws[d*12];
            float4 wa = dw[0], wb = dw[1], wc = dw[2];
            float a = bsm[d];
            a = fmaf(wa.x, dblS[0*DSTR+p],  a); a = fmaf(wa.y, dblS[1*DSTR+p],  a);
            a = fmaf(wa.z, dblS[2*DSTR+p],  a); a = fmaf(wa.w, dblS[3*DSTR+p],  a);
            a = fmaf(wb.x, dblS[4*DSTR+p],  a); a = fmaf(wb.y, dblS[5*DSTR+p],  a);
            a = fmaf(wb.z, dblS[6*DSTR+p],  a); a = fmaf(wb.w, dblS[7*DSTR+p],  a);
            a = fmaf(wc.x, dblS[8*DSTR+p],  a); a = fmaf(wc.y, dblS[9*DSTR+p],  a);
            a = fmaf(wc.z, dblS[10*DSTR+p], a); a = fmaf(wc.w, dblS[11*DSTR+p], a);
            float em = ex2(-fabsf(a) * LOG2E);
            float sp = fmaxf(a, 0.f) + lg2(1.f + em) * LN2;
            float z  = sp * xs[p*XSTR + d];
            int tauv = tau_of(k, pos0 + p);
            g_dz[((sbk48 + (d >> 2))*LLP + tauv)*4 + (d & 3)] = make_float2(sp, z);
        }
    }
}

// ---------------- kernel 2: selective scan ----------------
// grid (12, K, SB), 128 threads, warps independent. Dense chunk-major dz tiles,
// butterfly reduce-scatter (14 SHFL/tile), dense chunk-major y stores.
__global__ void __launch_bounds__(128) scan_kernel(const float* __restrict__ A1,
                                                   const float* __restrict__ A2)
{
    __shared__ float2 s_dz[4][4][ST*4];   // [warp][stage]  8 KB
    __shared__ float4 s_bc[4][4][ST*8];   // [warp][stage] 32 KB

    const int tid  = threadIdx.x;
    const int w    = tid >> 5;
    const int lane = tid & 31;
    const int dl = lane >> 3, no = lane & 7;
    const int k  = blockIdx.y;
    const int sb = blockIdx.z;
    const int s  = sb >> 1;
    const int d0 = blockIdx.x*16 + w*4;
    const int d  = d0 + dl;

    const float* Alog = s ? A2 : A1;
    const float a0 = -__expf(Alog[(k*Dd + d)*Nn + no    ]) * LOG2E;
    const float a1 = -__expf(Alog[(k*Dd + d)*Nn + no + 8]) * LOG2E;

    const int row0 = (sb*Kk + k)*LL;
    const size_t chn = (size_t)(sb*Kk + k)*48 + (d0 >> 2);
    const float2* dz_src = g_dz + chn*LLP*4 + lane*2;       // tile stride: 64 float2
    const float4* bc_src = (const float4*)g_BC + (size_t)row0*8 + lane;
    float* yp = g_yk + chn*(size_t)LL*4 + dl;

    // this lane's output steps after the reduce-scatter (s0, s0+1)
    const int s0 = ((no & 1) << 3) | ((no & 2) << 1) | ((no & 4) >> 1);

    #define LOAD_TILE(slot, tile) do {                                                   \
        unsigned za = (unsigned)__cvta_generic_to_shared(&s_dz[w][slot][2*lane]);        \
        asm volatile("cp.async.cg.shared.global [%0], [%1], 16;" ::                      \
                     "r"(za), "l"(dz_src + (size_t)(tile)*64));                          \
        _Pragma("unroll")                                                                \
        for (int q = 0; q < 4; q++) {                                                    \
            unsigned ba = (unsigned)__cvta_generic_to_shared(&s_bc[w][slot][q*32+lane]); \
            asm volatile("cp.async.cg.shared.global [%0], [%1], 16;" ::                  \
                         "r"(ba), "l"(bc_src + (size_t)(tile)*ST*8 + q*32));             \
        }                                                                                \
        asm volatile("cp.async.commit_group;");                                          \
    } while (0)

    LOAD_TILE(0, 0);
    LOAD_TILE(1, 1);
    LOAD_TILE(2, 2);

    float h0 = 0.f, h1 = 0.f;
    for (int it = 0; it < NT; it++) {
        const int slot = it & 3;
        const int tt = it * ST;
        asm volatile("cp.async.wait_group 2;");
        __syncwarp();
        LOAD_TILE((it + 3) & 3, it + 3);    // pad regions cover the tail tiles

        float yy[16];
        #pragma unroll
        for (int hb = 0; hb < 2; hb++) {
            float2 dzr[8]; float4 bcr[8];
            #pragma unroll
            for (int j = 0; j < 8; j++) {
                dzr[j] = s_dz[w][slot][(hb*8 + j)*4 + dl];
                bcr[j] = s_bc[w][slot][(hb*8 + j)*8 + no];
            }
            float e0[8], e1[8];
            #pragma unroll
            for (int j = 0; j < 8; j++) {
                e0[j] = ex2(dzr[j].x * a0);
                e1[j] = ex2(dzr[j].x * a1);
            }
            #pragma unroll
            for (int j = 0; j < 8; j++) {
                h0 = fmaf(e0[j], h0, dzr[j].y * bcr[j].x);
                h1 = fmaf(e1[j], h1, dzr[j].y * bcr[j].y);
                yy[hb*8 + j] = fmaf(h1, bcr[j].w, h0 * bcr[j].z);
            }
        }

        // butterfly reduce-scatter over the 8 n-lanes of each d-group
        #pragma unroll
        for (int j = 0; j < 8; j++) {
            float send = (no & 1) ? yy[j] : yy[8 + j];
            float recv = __shfl_xor_sync(0xffffffffu, send, 1);
            yy[j] = ((no & 1) ? yy[8 + j] : yy[j]) + recv;
        }
        #pragma unroll
        for (int j = 0; j < 4; j++) {
            float send = (no & 2) ? yy[j] : yy[4 + j];
            float recv = __shfl_xor_sync(0xffffffffu, send, 2);
            yy[j] = ((no & 2) ? yy[4 + j] : yy[j]) + recv;
        }
        #pragma unroll
        for (int j = 0; j < 2; j++) {
            float send = (no & 4) ? yy[j] : yy[2 + j];
            float recv = __shfl_xor_sync(0xffffffffu, send, 4);
            yy[j] = ((no & 4) ? yy[2 + j] : yy[j]) + recv;
        }
        // dense stores: warp covers floats [tt*4, tt*4+64)
        yp[(size_t)(tt + s0    )*4] = yy[0];
        yp[(size_t)(tt + s0 + 1)*4] = yy[1];
    }
    asm volatile("cp.async.wait_group 0;");
    #undef LOAD_TILE
}

// ---------------- kernel 3: merge (sum k) + D*u + LayerNorm ----------------
__global__ void merge_ln_kernel(const float* __restrict__ D1s, const float* __restrict__ D2s,
                                const float* __restrict__ lnw, const float* __restrict__ lnb,
                                float* __restrict__ out)
{
    __shared__ float red[6];
    const int rid = blockIdx.x;
    const int sb = rid / LL, pos = rid % LL;
    const int s = sb >> 1;
    const int d = threadIdx.x;
    const float* Ds = s ? D2s : D1s;

    const int t1 = (pos % Ww) * Hh + pos / Ww;
    const size_t kb = (size_t)(sb*Kk)*48;
    const int dc = d >> 2, dr = d & 3;

    #define YIDX(KK, TT) (((kb + (KK)*48 + dc)*(size_t)LL + (TT))*4 + dr)
    float v = g_yk[YIDX(0, pos)]
            + g_yk[YIDX(1, t1)]
            + g_yk[YIDX(2, LL-1-pos)]
            + g_yk[YIDX(3, LL-1-t1)];
    #undef YIDX
    const float Dsum = Ds[d] + Ds[Dd + d] + Ds[2*Dd + d] + Ds[3*Dd + d];
    v = fmaf(Dsum, g_xT[(size_t)(sb*LL + pos)*Dd + d], v);

    float tsum = v;
    #pragma unroll
    for (int o = 16; o; o >>= 1) tsum += __shfl_xor_sync(0xffffffffu, tsum, o);
    if ((d & 31) == 0) red[d >> 5] = tsum;
    __syncthreads();
    const float mu = (red[0]+red[1]+red[2]+red[3]+red[4]+red[5]) * (1.f/192.f);
    const float dv = v - mu;
    __syncthreads();
    float q = dv*dv;
    #pragma unroll
    for (int o = 16; o; o >>= 1) q += __shfl_xor_sync(0xffffffffu, q, o);
    if ((d & 31) == 0) red[d >> 5] = q;
    __syncthreads();
    const float var = (red[0]+red[1]+red[2]+red[3]+red[4]+red[5]) * (1.f/192.f);

    out[rid*Dd + d] = dv * rsqrtf(var + 1e-5f) * lnw[d] + lnb[d];
}

// ---------------- launch ----------------
extern "C" void kernel_launch(void* const* d_in, const int* in_sizes, int n_in,
                              void* d_out, int out_size)
{
    const float* x1   = (const float*)d_in[0];
    const float* x2   = (const float*)d_in[1];
    const float* pw1  = (const float*)d_in[2];
    const float* pw2  = (const float*)d_in[3];
    const float* dtw1 = (const float*)d_in[4];
    const float* dtw2 = (const float*)d_in[5];
    const float* dtb1 = (const float*)d_in[6];
    const float* dtb2 = (const float*)d_in[7];
    const float* A1   = (const float*)d_in[8];
    const float* A2   = (const float*)d_in[9];
    const float* D1s  = (const float*)d_in[10];
    const float* D2s  = (const float*)d_in[11];
    const float* lnw  = (const float*)d_in[12];
    const float* lnb  = (const float*)d_in[13];
    float* out = (float*)d_out;

    const int smem = (TP*XSTR + CHP*Dd + Dd*12 + Dd + CHP*DSTR) * (int)sizeof(float); // 109,696 B
    cudaFuncSetAttribute(prep_kernel, cudaFuncAttributeMaxDynamicSharedMemorySize, smem);

    prep_kernel<<<dim3(LL/TP, Kk, 4), 256, smem>>>(x1, x2, pw1, pw2, dtw1, dtw2, dtb1, dtb2);
    scan_kernel<<<dim3(Dd/16, Kk, 2*Bb), 128>>>(A1, A2);
    merge_ln_kernel<<<2*Bb*LL, Dd>>>(D1s, D2s, lnw, lnb, out);
}

// round 11
// speedup vs baseline: 1.4315x; 1.0149x over previous
#include <cuda_runtime.h>
#include <math.h>

#define Bb 2
#define Dd 192
#define Hh 56
#define Ww 56
#define Nn 16
#define Rr 12
#define Kk 4
#define LL (Hh*Ww)      /* 3136 */
#define LLP 3200        /* padded chain length for dz (prefetch overrun) */
#define TP 64           /* positions per prep tile */
#define CH 44           /* R + 2N */
#define CHP 48          /* padded channels */
#define PF 64           /* BC prefetch pad rows */
#define XSTR 196        /* xs smem row stride (words) */
#define DSTR 66         /* dblS row stride */
#define ST 16           /* scan steps per tile */
#define NT (LL/ST)      /* 196 tiles */
#define NPREP 784       /* prep blocks */
#define NSCAN 192       /* scan blocks */

typedef unsigned long long u64;

// ---------------- device scratch (static, no runtime alloc) ----------------
__device__ float2 g_dz[16*48*LLP*4];             // chunk-major (softplus, delta*u)
__device__ float2 g_BC[2*Bb*Kk*LL*16 + PF*16];   // per (row,no): {B_no,B_no+8},{C_no,C_no+8}
__device__ float  g_yk[16*48*LL*4];              // chunk-major scan outputs
__device__ float  g_xT[2*Bb*LL*Dd];              // x transposed to [pos][d]
__device__ int    g_prep_cnt[8];                 // per-(b,k) prep completion counters

__device__ __forceinline__ float ex2(float x) {
    float r; asm("ex2.approx.ftz.f32 %0, %1;" : "=f"(r) : "f"(x)); return r;
}
__device__ __forceinline__ float lg2(float x) {
    float r; asm("lg2.approx.ftz.f32 %0, %1;" : "=f"(r) : "f"(x)); return r;
}
__device__ __forceinline__ u64 ffma2(u64 a, u64 b, u64 c) {
    u64 r; asm("fma.rn.f32x2 %0, %1, %2, %3;" : "=l"(r) : "l"(a), "l"(b), "l"(c)); return r;
}
__device__ __forceinline__ float hadd2(u64 v) {
    float lo, hi; asm("mov.b64 {%0, %1}, %2;" : "=f"(lo), "=f"(hi) : "l"(v)); return lo + hi;
}
#define LOG2E 1.44269504088896340736f
#define LN2   0.69314718055994530942f

__device__ __forceinline__ int tau_of(int k, int pos) {
    int t1 = (pos % Ww) * Hh + pos / Ww;
    switch (k) {
        case 0: return pos;
        case 1: return t1;
        case 2: return LL - 1 - pos;
        default: return LL - 1 - t1;
    }
}

// ---------------- kernel 0: capture-safe counter reset ----------------
__global__ void zero_cnt_kernel()
{
    if (threadIdx.x < 8) g_prep_cnt[threadIdx.x] = 0;
}

// ================= fused kernel: prep blocks + scan blocks =================
__global__ void __launch_bounds__(256, 2)
fused_kernel(const float* __restrict__ x1, const float* __restrict__ x2,
             const float* __restrict__ pw1, const float* __restrict__ pw2,
             const float* __restrict__ dtw1, const float* __restrict__ dtw2,
             const float* __restrict__ dtb1, const float* __restrict__ dtb2,
             const float* __restrict__ A1, const float* __restrict__ A2)
{
    extern __shared__ float sm[];
    const int bid = blockIdx.x;
    const int t   = threadIdx.x;

    if (bid < NPREP) {
        // ---------------- PREP phase ----------------
        const int g    = bid / 98;            // (b,k) group
        const int b    = g >> 2;
        const int k    = g & 3;
        const int rem  = bid - g*98;
        const int s    = rem / 49;
        const int pos0 = (rem - s*49) * TP;

        float* xs   = sm;                    // [TP][XSTR]
        float* Ws   = xs + TP*XSTR;          // [48][192]
        float* dtws = Ws + CHP*Dd;           // [192][12]
        float* bsm  = dtws + Dd*12;          // [192]
        float* dblS = bsm + Dd;              // [48][DSTR]

        const float* x   = s ? x2   : x1;
        const float* pw  = s ? pw2  : pw1;
        const float* dtw = s ? dtw2 : dtw1;
        const float* dtb = s ? dtb2 : dtb1;
        const int sb  = s*2 + b;
        const int sbo = (s^1)*2 + b;

        for (int e = t; e < Dd*(TP/4); e += 256) {
            int d = e >> 4, p4 = (e & 15) * 4;
            float4 v = *(const float4*)&x[(size_t)(b*Dd + d)*LL + pos0 + p4];
            xs[(p4+0)*XSTR + d] = v.x;
            xs[(p4+1)*XSTR + d] = v.y;
            xs[(p4+2)*XSTR + d] = v.z;
            xs[(p4+3)*XSTR + d] = v.w;
        }
        for (int e = t; e < CHP*Dd/4; e += 256) {
            float4 v = (e < CH*Dd/4) ? ((const float4*)pw)[(size_t)k*(CH*Dd/4) + e]
                                     : make_float4(0.f,0.f,0.f,0.f);
            ((float4*)Ws)[e] = v;
        }
        for (int e = t; e < Dd*Rr/4; e += 256)
            ((float4*)dtws)[e] = ((const float4*)dtw)[(size_t)k*(Dd*Rr/4) + e];
        if (t < Dd) bsm[t] = dtb[k*Dd + t];
        __syncthreads();

        if (k == 0) {
            for (int e = t; e < TP*Dd; e += 256) {
                int p = e / Dd, d = e - p*Dd;
                g_xT[(size_t)(sb*LL + pos0 + p)*Dd + d] = xs[p*XSTR + d];
            }
        }

        const int pg = t & 15;
        const int cb = t >> 4;

        {   // GEMM: dbl[c][p] = sum_d W[c][d] * x[d][p]
            u64 acc2[4][3];
            #pragma unroll
            for (int i = 0; i < 4; i++)
                #pragma unroll
                for (int j = 0; j < 3; j++) acc2[i][j] = 0ull;

            #pragma unroll 2
            for (int d4 = 0; d4 < Dd; d4 += 4) {
                ulonglong2 w0 = *(const ulonglong2*)&Ws[ cb      *Dd + d4];
                ulonglong2 w1 = *(const ulonglong2*)&Ws[(cb+16) *Dd + d4];
                ulonglong2 w2 = *(const ulonglong2*)&Ws[(cb+32) *Dd + d4];
                #pragma unroll
                for (int i = 0; i < 4; i++) {
                    ulonglong2 xv = *(const ulonglong2*)&xs[(pg + 16*i)*XSTR + d4];
                    acc2[i][0] = ffma2(xv.x, w0.x, acc2[i][0]);
                    acc2[i][0] = ffma2(xv.y, w0.y, acc2[i][0]);
                    acc2[i][1] = ffma2(xv.x, w1.x, acc2[i][1]);
                    acc2[i][1] = ffma2(xv.y, w1.y, acc2[i][1]);
                    acc2[i][2] = ffma2(xv.x, w2.x, acc2[i][2]);
                    acc2[i][2] = ffma2(xv.y, w2.y, acc2[i][2]);
                }
            }
            #pragma unroll
            for (int i = 0; i < 4; i++) {
                dblS[ cb     *DSTR + pg + 16*i] = hadd2(acc2[i][0]);
                dblS[(cb+16) *DSTR + pg + 16*i] = hadd2(acc2[i][1]);
                dblS[(cb+32) *DSTR + pg + 16*i] = hadd2(acc2[i][2]);
            }
        }
        __syncthreads();

        // packed B(own)/C(cross), traversal order, n-paired (no, no+8)
        for (int e = t; e < TP*8; e += 256) {
            int p = e >> 3, no = e & 7;
            int tauv = tau_of(k, pos0 + p);
            float2 bv = make_float2(dblS[(12+no)*DSTR+p], dblS[(20+no)*DSTR+p]);
            float2 cv = make_float2(dblS[(28+no)*DSTR+p], dblS[(36+no)*DSTR+p]);
            g_BC[((size_t)(sb *Kk + k)*LL + tauv)*16 + no*2    ] = bv;
            g_BC[((size_t)(sbo*Kk + k)*LL + tauv)*16 + no*2 + 1] = cv;
        }

        // dt epilogue; chunk-major dz store
        {
            const size_t sbk48 = (size_t)(sb*Kk + k)*48;
            for (int e = t; e < TP*Dd; e += 256) {
                int p = e / Dd, d = e - p*Dd;
                const float4* dw = (const float4*)&dtws[d*12];
                float4 wa = dw[0], wb = dw[1], wc = dw[2];
                float a = bsm[d];
                a = fmaf(wa.x, dblS[0*DSTR+p],  a); a = fmaf(wa.y, dblS[1*DSTR+p],  a);
                a = fmaf(wa.z, dblS[2*DSTR+p],  a); a = fmaf(wa.w, dblS[3*DSTR+p],  a);
                a = fmaf(wb.x, dblS[4*DSTR+p],  a); a = fmaf(wb.y, dblS[5*DSTR+p],  a);
                a = fmaf(wb.z, dblS[6*DSTR+p],  a); a = fmaf(wb.w, dblS[7*DSTR+p],  a);
                a = fmaf(wc.x, dblS[8*DSTR+p],  a); a = fmaf(wc.y, dblS[9*DSTR+p],  a);
                a = fmaf(wc.z, dblS[10*DSTR+p], a); a = fmaf(wc.w, dblS[11*DSTR+p], a);
                float em = ex2(-fabsf(a) * LOG2E);
                float sp = fmaxf(a, 0.f) + lg2(1.f + em) * LN2;
                float z  = sp * xs[p*XSTR + d];
                int tauv = tau_of(k, pos0 + p);
                g_dz[((sbk48 + (d >> 2))*LLP + tauv)*4 + (d & 3)] = make_float2(sp, z);
            }
        }

        // signal completion (release)
        __threadfence();
        __syncthreads();
        if (t == 0) atomicAdd(&g_prep_cnt[g], 1);
        return;
    }

    // ---------------- SCAN phase ----------------
    {
        const int sid  = bid - NPREP;
        const int g    = sid / 24;            // (b,k) group (matches prep ordering)
        const int b    = g >> 2;
        const int k    = g & 3;
        const int rem  = sid - g*24;
        const int s    = rem / 12;
        const int chunk= rem - s*12;
        const int sb   = s*2 + b;

        // gate: wait for this (b,k) group's 98 prep blocks (covers B, C, dz)
        if (t == 0) {
            volatile int* c = (volatile int*)&g_prep_cnt[g];
            while (*c < 98) __nanosleep(128);
        }
        __syncthreads();
        __threadfence();
        if (t >= 128) return;                 // 4 working warps

        float2* s_dz = (float2*)sm;           // [4][4][64]   8 KB
        float4* s_bc = (float4*)(sm + 2048);  // [4][4][128] 32 KB

        const int w    = t >> 5;
        const int lane = t & 31;
        const int dl = lane >> 3, no = lane & 7;
        const int d0 = chunk*16 + w*4;
        const int d  = d0 + dl;

        const float* Alog = s ? A2 : A1;
        const float a0 = -__expf(Alog[(k*Dd + d)*Nn + no    ]) * LOG2E;
        const float a1 = -__expf(Alog[(k*Dd + d)*Nn + no + 8]) * LOG2E;

        const int row0 = (sb*Kk + k)*LL;
        const size_t chn = (size_t)(sb*Kk + k)*48 + (d0 >> 2);
        const float2* dz_src = g_dz + chn*LLP*4 + lane*2;       // tile stride 64 float2
        const float4* bc_src = (const float4*)g_BC + (size_t)row0*8 + lane;
        float* yp = g_yk + chn*(size_t)LL*4 + dl;

        const int s0 = ((no & 1) << 3) | ((no & 2) << 1) | ((no & 4) >> 1);

        #define LOAD_TILE(slot, tile) do {                                                     \
            unsigned za = (unsigned)__cvta_generic_to_shared(&s_dz[(w*4+(slot))*64 + 2*lane]); \
            asm volatile("cp.async.cg.shared.global [%0], [%1], 16;" ::                        \
                         "r"(za), "l"(dz_src + (size_t)(tile)*64));                            \
            _Pragma("unroll")                                                                  \
            for (int q = 0; q < 4; q++) {                                                      \
                unsigned ba = (unsigned)__cvta_generic_to_shared(                              \
                                  &s_bc[(w*4+(slot))*128 + q*32 + lane]);                      \
                asm volatile("cp.async.cg.shared.global [%0], [%1], 16;" ::                    \
                             "r"(ba), "l"(bc_src + (size_t)(tile)*ST*8 + q*32));               \
            }                                                                                  \
            asm volatile("cp.async.commit_group;");                                            \
        } while (0)

        LOAD_TILE(0, 0);
        LOAD_TILE(1, 1);
        LOAD_TILE(2, 2);

        float h0 = 0.f, h1 = 0.f;
        for (int it = 0; it < NT; it++) {
            const int slot = it & 3;
            const int tt = it * ST;
            asm volatile("cp.async.wait_group 2;");
            __syncwarp();
            LOAD_TILE((it + 3) & 3, it + 3);

            float yy[16];
            #pragma unroll
            for (int hb = 0; hb < 2; hb++) {
                float2 dzr[8]; float4 bcr[8];
                #pragma unroll
                for (int j = 0; j < 8; j++) {
                    dzr[j] = s_dz[(w*4+slot)*64 + (hb*8 + j)*4 + dl];
                    bcr[j] = s_bc[(w*4+slot)*128 + (hb*8 + j)*8 + no];
                }
                float e0[8], e1[8];
                #pragma unroll
                for (int j = 0; j < 8; j++) {
                    e0[j] = ex2(dzr[j].x * a0);
                    e1[j] = ex2(dzr[j].x * a1);
                }
                #pragma unroll
                for (int j = 0; j < 8; j++) {
                    h0 = fmaf(e0[j], h0, dzr[j].y * bcr[j].x);
                    h1 = fmaf(e1[j], h1, dzr[j].y * bcr[j].y);
                    yy[hb*8 + j] = fmaf(h1, bcr[j].w, h0 * bcr[j].z);
                }
            }
            #pragma unroll
            for (int j = 0; j < 8; j++) {
                float send = (no & 1) ? yy[j] : yy[8 + j];
                float recv = __shfl_xor_sync(0xffffffffu, send, 1);
                yy[j] = ((no & 1) ? yy[8 + j] : yy[j]) + recv;
            }
            #pragma unroll
            for (int j = 0; j < 4; j++) {
                float send = (no & 2) ? yy[j] : yy[4 + j];
                float recv = __shfl_xor_sync(0xffffffffu, send, 2);
                yy[j] = ((no & 2) ? yy[4 + j] : yy[j]) + recv;
            }
            #pragma unroll
            for (int j = 0; j < 2; j++) {
                float send = (no & 4) ? yy[j] : yy[2 + j];
                float recv = __shfl_xor_sync(0xffffffffu, send, 4);
                yy[j] = ((no & 4) ? yy[2 + j] : yy[j]) + recv;
            }
            yp[(size_t)(tt + s0    )*4] = yy[0];
            yp[(size_t)(tt + s0 + 1)*4] = yy[1];
        }
        asm volatile("cp.async.wait_group 0;");
        #undef LOAD_TILE
    }
}

// ---------------- kernel 2: merge (sum k) + D*u + LayerNorm ----------------
__global__ void merge_ln_kernel(const float* __restrict__ D1s, const float* __restrict__ D2s,
                                const float* __restrict__ lnw, const float* __restrict__ lnb,
                                float* __restrict__ out)
{
    __shared__ float red[6];
    const int rid = blockIdx.x;
    const int sb = rid / LL, pos = rid % LL;
    const int s = sb >> 1;
    const int d = threadIdx.x;
    const float* Ds = s ? D2s : D1s;

    const int t1 = (pos % Ww) * Hh + pos / Ww;
    const size_t kb = (size_t)(sb*Kk)*48;
    const int dc = d >> 2, dr = d & 3;

    #define YIDX(KK, TT) (((kb + (KK)*48 + dc)*(size_t)LL + (TT))*4 + dr)
    float v = g_yk[YIDX(0, pos)]
            + g_yk[YIDX(1, t1)]
            + g_yk[YIDX(2, LL-1-pos)]
            + g_yk[YIDX(3, LL-1-t1)];
    #undef YIDX
    const float Dsum = Ds[d] + Ds[Dd + d] + Ds[2*Dd + d] + Ds[3*Dd + d];
    v = fmaf(Dsum, g_xT[(size_t)(sb*LL + pos)*Dd + d], v);

    float tsum = v;
    #pragma unroll
    for (int o = 16; o; o >>= 1) tsum += __shfl_xor_sync(0xffffffffu, tsum, o);
    if ((d & 31) == 0) red[d >> 5] = tsum;
    __syncthreads();
    const float mu = (red[0]+red[1]+red[2]+red[3]+red[4]+red[5]) * (1.f/192.f);
    const float dv = v - mu;
    __syncthreads();
    float q = dv*dv;
    #pragma unroll
    for (int o = 16; o; o >>= 1) q += __shfl_xor_sync(0xffffffffu, q, o);
    if ((d & 31) == 0) red[d >> 5] = q;
    __syncthreads();
    const float var = (red[0]+red[1]+red[2]+red[3]+red[4]+red[5]) * (1.f/192.f);

    out[rid*Dd + d] = dv * rsqrtf(var + 1e-5f) * lnw[d] + lnb[d];
}

// ---------------- launch ----------------
extern "C" void kernel_launch(void* const* d_in, const int* in_sizes, int n_in,
                              void* d_out, int out_size)
{
    const float* x1   = (const float*)d_in[0];
    const float* x2   = (const float*)d_in[1];
    const float* pw1  = (const float*)d_in[2];
    const float* pw2  = (const float*)d_in[3];
    const float* dtw1 = (const float*)d_in[4];
    const float* dtw2 = (const float*)d_in[5];
    const float* dtb1 = (const float*)d_in[6];
    const float* dtb2 = (const float*)d_in[7];
    const float* A1   = (const float*)d_in[8];
    const float* A2   = (const float*)d_in[9];
    const float* D1s  = (const float*)d_in[10];
    const float* D2s  = (const float*)d_in[11];
    const float* lnw  = (const float*)d_in[12];
    const float* lnb  = (const float*)d_in[13];
    float* out = (float*)d_out;

    const int smem = (TP*XSTR + CHP*Dd + Dd*12 + Dd + CHP*DSTR) * (int)sizeof(float); // 109,696 B
    cudaFuncSetAttribute(fused_kernel, cudaFuncAttributeMaxDynamicSharedMemorySize, smem);

    zero_cnt_kernel<<<1, 32>>>();
    fused_kernel<<<NPREP + NSCAN, 256, smem>>>(x1, x2, pw1, pw2, dtw1, dtw2,
                                               dtb1, dtb2, A1, A2);
    merge_ln_kernel<<<2*Bb*LL, Dd>>>(D1s, D2s, lnw, lnb, out);
}